// round 1
// baseline (speedup 1.0000x reference)
#include <cuda_runtime.h>
#include <math.h>

#define BATCH 2
#define T 2048
#define DM 1024
#define NH 16
#define DK 64
#define RR 8
#define LORA_SCALE 2.0f      // ALPHA/R = 16/8
#define MTOT (BATCH*T)       // 4096

// ---------------- scratch (device globals; no allocs allowed) ----------------
__device__ float g_weff[3][DM*DM];                 // folded LoRA weights q,k,v
__device__ float g_qkv[3][BATCH*NH*T*DK];          // Q,K,V in (b,h,t,d) layout
__device__ float g_attn[BATCH*T*DM];               // attention out, (b,t,d)

// ---------------- W_eff = W + scale * B @ A ----------------
__global__ void weff_kernel(const float* __restrict__ W,
                            const float* __restrict__ A,
                            const float* __restrict__ Bm,
                            float* __restrict__ out) {
    int idx = blockIdx.x * 256 + threadIdx.x;      // 0 .. 1024*1024-1
    int o = idx >> 10;
    int d = idx & 1023;
    float s = 0.f;
#pragma unroll
    for (int r = 0; r < RR; r++) s += Bm[o*RR + r] * A[r*DM + d];
    out[idx] = W[idx] + LORA_SCALE * s;
}

// ---------------- SGEMM: C[m,n] = sum_k A[m,k]*W[n,k] + bias[n] --------------
// A: (MTOT, DM) row-major, W: (DM, DM) row-major (N-major "NT" gemm).
// mode 0: C[m*DM+n]   (plain, for output projection)
// mode 1: C written in (b,h,t,dk) layout for attention consumption
__global__ __launch_bounds__(256)
void sgemm_nt(const float* __restrict__ A, const float* __restrict__ W,
              const float* __restrict__ bias, float* __restrict__ C,
              int mode) {
    __shared__ float As[64][17];
    __shared__ float Bs[64][17];
    const int tx = threadIdx.x & 15;
    const int ty = threadIdx.x >> 4;
    const int row0 = blockIdx.y * 64;
    const int col0 = blockIdx.x * 64;
    float acc[4][4] = {};

    const int ldm = threadIdx.x >> 2;              // 0..63
    const int kk4 = (threadIdx.x & 3) * 4;         // 0,4,8,12

    for (int k0 = 0; k0 < DM; k0 += 16) {
        float4 a4 = *(const float4*)(A + (size_t)(row0 + ldm)*DM + k0 + kk4);
        As[ldm][kk4+0] = a4.x; As[ldm][kk4+1] = a4.y;
        As[ldm][kk4+2] = a4.z; As[ldm][kk4+3] = a4.w;
        float4 b4 = *(const float4*)(W + (size_t)(col0 + ldm)*DM + k0 + kk4);
        Bs[ldm][kk4+0] = b4.x; Bs[ldm][kk4+1] = b4.y;
        Bs[ldm][kk4+2] = b4.z; Bs[ldm][kk4+3] = b4.w;
        __syncthreads();
#pragma unroll
        for (int kk = 0; kk < 16; kk++) {
            float a[4], b[4];
#pragma unroll
            for (int i = 0; i < 4; i++) a[i] = As[ty*4 + i][kk];
#pragma unroll
            for (int j = 0; j < 4; j++) b[j] = Bs[tx*4 + j][kk];
#pragma unroll
            for (int i = 0; i < 4; i++)
#pragma unroll
                for (int j = 0; j < 4; j++)
                    acc[i][j] += a[i] * b[j];
        }
        __syncthreads();
    }

#pragma unroll
    for (int i = 0; i < 4; i++) {
        int m = row0 + ty*4 + i;
#pragma unroll
        for (int j = 0; j < 4; j++) {
            int n = col0 + tx*4 + j;
            float v = acc[i][j] + bias[n];
            if (mode == 0) {
                C[(size_t)m*DM + n] = v;
            } else {
                int bb = m >> 11, t = m & (T-1);
                int h  = n >> 6,  dk = n & (DK-1);
                C[(((size_t)(bb*NH + h))*T + t)*DK + dk] = v;
            }
        }
    }
}

// ---------------- Flash attention: 1 thread = 1 query row --------------------
// Q,K,V in (b,h,t,d). O written to (b,t,h*64+d) so the output GEMM reads it
// as a plain (4096,1024) matrix.
__global__ __launch_bounds__(128, 2)
void flash_attn(const float* __restrict__ Q, const float* __restrict__ K,
                const float* __restrict__ V, const int* __restrict__ mask,
                float* __restrict__ O) {
    const int qt = blockIdx.x, h = blockIdx.y, b = blockIdx.z;
    const int bh = b*NH + h;
    const int tid = threadIdx.x;
    const int q = qt*128 + tid;                    // query t index

    __shared__ float Ks[32][DK];
    __shared__ float Vs[32][DK];

    float qreg[DK];
    const float* qrow = Q + ((size_t)bh*T + q)*DK;
#pragma unroll
    for (int d = 0; d < DK; d += 4) {
        float4 v4 = *(const float4*)(qrow + d);
        qreg[d] = v4.x; qreg[d+1] = v4.y; qreg[d+2] = v4.z; qreg[d+3] = v4.w;
    }
    float acc[DK];
#pragma unroll
    for (int d = 0; d < DK; d++) acc[d] = 0.f;
    float mval = -1e30f, l = 0.f;

    const float* Kb = K + (size_t)bh*T*DK;
    const float* Vb = V + (size_t)bh*T*DK;
    const int*   mrow = mask + (size_t)q*T;

    for (int k0 = 0; k0 < T; k0 += 32) {
        __syncthreads();
        // cooperative load of 32x64 K and V tiles (512 float4 each)
        for (int i = tid; i < 512; i += 128) {
            int r = i >> 4;
            int c = (i & 15) << 2;
            *(float4*)&Ks[r][c] = *(const float4*)(Kb + (size_t)(k0+r)*DK + c);
            *(float4*)&Vs[r][c] = *(const float4*)(Vb + (size_t)(k0+r)*DK + c);
        }
        __syncthreads();

        float s[32];
#pragma unroll
        for (int j = 0; j < 32; j++) {
            float sv = 0.f;
#pragma unroll
            for (int d = 0; d < DK; d += 4) {
                float4 kv = *(const float4*)&Ks[j][d];
                sv += qreg[d]*kv.x + qreg[d+1]*kv.y
                    + qreg[d+2]*kv.z + qreg[d+3]*kv.w;
            }
            s[j] = (mrow[k0 + j] == 0) ? -1e9f : sv * 0.125f; // 1/sqrt(64)
        }
        float tm = mval;
#pragma unroll
        for (int j = 0; j < 32; j++) tm = fmaxf(tm, s[j]);
        float corr = __expf(mval - tm);
        mval = tm;
        l *= corr;
#pragma unroll
        for (int d = 0; d < DK; d++) acc[d] *= corr;
#pragma unroll
        for (int j = 0; j < 32; j++) {
            float p = __expf(s[j] - tm);
            l += p;
#pragma unroll
            for (int d = 0; d < DK; d += 4) {
                float4 vv = *(const float4*)&Vs[j][d];
                acc[d]   += p*vv.x; acc[d+1] += p*vv.y;
                acc[d+2] += p*vv.z; acc[d+3] += p*vv.w;
            }
        }
    }

    const float inv = 1.f / l;
    float* orow = O + ((size_t)(b*T + q))*DM + h*DK;
#pragma unroll
    for (int d = 0; d < DK; d += 4) {
        float4 o4 = make_float4(acc[d]*inv, acc[d+1]*inv, acc[d+2]*inv, acc[d+3]*inv);
        *(float4*)(orow + d) = o4;
    }
}

// ---------------- launch ----------------
extern "C" void kernel_launch(void* const* d_in, const int* in_sizes, int n_in,
                              void* d_out, int out_size) {
    const float* q    = (const float*)d_in[0];
    const float* k    = (const float*)d_in[1];
    const float* v    = (const float*)d_in[2];
    const int*   mask = (const int*)  d_in[3];
    const float* Wq = (const float*)d_in[4],  *bq = (const float*)d_in[5];
    const float* Aq = (const float*)d_in[6],  *Bq = (const float*)d_in[7];
    const float* Wk = (const float*)d_in[8],  *bk = (const float*)d_in[9];
    const float* Ak = (const float*)d_in[10], *Bk = (const float*)d_in[11];
    const float* Wv = (const float*)d_in[12], *bv = (const float*)d_in[13];
    const float* Av = (const float*)d_in[14], *Bv = (const float*)d_in[15];
    const float* Wo = (const float*)d_in[16], *bo = (const float*)d_in[17];
    float* out = (float*)d_out;

    float *weff, *qkv, *attn;
    cudaGetSymbolAddress((void**)&weff, g_weff);
    cudaGetSymbolAddress((void**)&qkv,  g_qkv);
    cudaGetSymbolAddress((void**)&attn, g_attn);
    float* weffq = weff;
    float* weffk = weff + (size_t)DM*DM;
    float* weffv = weff + (size_t)2*DM*DM;
    const size_t QKV_SZ = (size_t)BATCH*NH*T*DK;
    float* Qp = qkv;
    float* Kp = qkv + QKV_SZ;
    float* Vp = qkv + 2*QKV_SZ;

    weff_kernel<<<DM*DM/256, 256>>>(Wq, Aq, Bq, weffq);
    weff_kernel<<<DM*DM/256, 256>>>(Wk, Ak, Bk, weffk);
    weff_kernel<<<DM*DM/256, 256>>>(Wv, Av, Bv, weffv);

    dim3 gg(DM/64, MTOT/64);
    sgemm_nt<<<gg, 256>>>(q, weffq, bq, Qp, 1);
    sgemm_nt<<<gg, 256>>>(k, weffk, bk, Kp, 1);
    sgemm_nt<<<gg, 256>>>(v, weffv, bv, Vp, 1);

    flash_attn<<<dim3(T/128, NH, BATCH), 128>>>(Qp, Kp, Vp, mask, attn);

    sgemm_nt<<<gg, 256>>>(attn, Wo, bo, out, 0);
}

// round 3
// speedup vs baseline: 1.3553x; 1.3553x over previous
#include <cuda_runtime.h>
#include <math.h>
#include <stdint.h>

#define BATCH 2
#define T 2048
#define DM 1024
#define NH 16
#define DK 64
#define RR 8
#define LORA_SCALE 2.0f
#define MTOT (BATCH*T)      // 4096

// ---------------- scratch (device globals; no allocs allowed) ----------------
__device__ float g_weff[3][DM*DM];            // folded + tf32-rounded LoRA weights
__device__ float g_wo[DM*DM];                 // tf32-rounded Wo
__device__ float g_qkv[3][BATCH*NH*T*DK];     // Q,K,V in (b,h,t,d)
__device__ float g_attn[MTOT*DM];             // attention out (tf32-rounded)

// ---------------- helpers ----------------
__device__ __forceinline__ float tf32r(float x) {
    uint32_t r;
    asm("cvt.rna.tf32.f32 %0, %1;" : "=r"(r) : "f"(x));
    return __uint_as_float(r);
}
__device__ __forceinline__ uint32_t tf32r_u(float x) {
    uint32_t r;
    asm("cvt.rna.tf32.f32 %0, %1;" : "=r"(r) : "f"(x));
    return r;
}
#define CP_ASYNC16(dst, src) \
    asm volatile("cp.async.cg.shared.global [%0], [%1], 16;" :: "r"(dst), "l"(src))
#define CP_COMMIT() asm volatile("cp.async.commit_group;" ::: "memory")
#define CP_WAIT(n)  asm volatile("cp.async.wait_group %0;" :: "n"(n) : "memory")

__device__ __forceinline__ uint32_t smem_u32(const void* p) {
    uint32_t a;
    asm("{ .reg .u64 t; cvta.to.shared.u64 t, %1; cvt.u32.u64 %0, t; }" : "=r"(a) : "l"(p));
    return a;
}

__device__ __forceinline__ void mma_tf32(float* c, const uint32_t* a, const uint32_t* b) {
    asm volatile(
        "mma.sync.aligned.m16n8k8.row.col.f32.tf32.tf32.f32 "
        "{%0,%1,%2,%3}, {%4,%5,%6,%7}, {%8,%9}, {%0,%1,%2,%3};"
        : "+f"(c[0]), "+f"(c[1]), "+f"(c[2]), "+f"(c[3])
        : "r"(a[0]), "r"(a[1]), "r"(a[2]), "r"(a[3]), "r"(b[0]), "r"(b[1]));
}

// ---------------- W_eff = tf32_round(W + scale * B @ A) ----------------
__global__ void weff_kernel(const float* __restrict__ W,
                            const float* __restrict__ A,
                            const float* __restrict__ Bm,
                            float* __restrict__ out) {
    int idx = blockIdx.x * 256 + threadIdx.x;
    int o = idx >> 10;
    int d = idx & 1023;
    float s = 0.f;
#pragma unroll
    for (int r = 0; r < RR; r++) s += Bm[o*RR + r] * A[r*DM + d];
    out[idx] = tf32r(W[idx] + LORA_SCALE * s);
}

__global__ void round_tf32_kernel(const float* __restrict__ in,
                                  float* __restrict__ out, int n4) {
    int i = blockIdx.x * 256 + threadIdx.x;
    if (i >= n4) return;
    float4 v = ((const float4*)in)[i];
    v.x = tf32r(v.x); v.y = tf32r(v.y); v.z = tf32r(v.z); v.w = tf32r(v.w);
    ((float4*)out)[i] = v;
}

// ---------------- mma.sync tf32 GEMM ----------------------------------------
// C[m,n] = sum_k A[m,k]*W[n,k] + bias[n]
// A:(MTOT,DM) rm fp32 (rounded in-register), W:(DM,DM) rm (pre-rounded tf32).
// CTA tile 128x128, 8 warps (2 M x 4 N), warp tile 64x32, KTILE=16, 2 stages.
#define KT 16
#define NIT (DM / KT)         // 64
#define SROW 20               // padded word stride (conflict-free)

__global__ __launch_bounds__(256, 2)
void gemm_mma(const float* __restrict__ A, const float* __restrict__ W,
              const float* __restrict__ bias, float* __restrict__ C, int mode) {
    __shared__ float As[2][128 * SROW];
    __shared__ float Bs[2][128 * SROW];

    const int tid = threadIdx.x;
    const int wid = tid >> 5;
    const int lane = tid & 31;
    const int wm = wid >> 2;          // 0..1
    const int wn = wid & 3;           // 0..3
    const int row0 = blockIdx.y * 128;
    const int col0 = blockIdx.x * 128;

    const uint32_t sa = smem_u32(&As[0][0]);
    const uint32_t sb = smem_u32(&Bs[0][0]);

    // per-thread cp.async indices: 512 float4 per operand tile, 256 threads
    const int e0 = tid * 2;           // 2 float4 each, rows interleaved
    float acc[4][4][4];
#pragma unroll
    for (int i = 0; i < 4; i++)
#pragma unroll
        for (int j = 0; j < 4; j++)
#pragma unroll
            for (int r = 0; r < 4; r++) acc[i][j][r] = 0.f;

    // ---- stage loader (cp.async) ----
    auto load_stage = [&](int st, int k0) {
#pragma unroll
        for (int i = 0; i < 2; i++) {
            int e = e0 + i;                 // 0..511
            int r = e >> 2;                 // row 0..127
            int c4 = (e & 3) * 4;           // k word 0,4,8,12
            uint32_t doff = (uint32_t)(r * SROW + c4) * 4;
            CP_ASYNC16(sa + (uint32_t)st * (128*SROW*4) + doff,
                       A + (size_t)(row0 + r) * DM + k0 + c4);
            CP_ASYNC16(sb + (uint32_t)st * (128*SROW*4) + doff,
                       W + (size_t)(col0 + r) * DM + k0 + c4);
        }
    };

    load_stage(0, 0);
    CP_COMMIT();

    const int arow = wm * 64 + (lane >> 2);     // base A row in tile
    const int bcol = wn * 32 + (lane >> 2);     // base B col(row of Bs)
    const int kq = lane & 3;

    for (int it = 0; it < NIT; it++) {
        if (it + 1 < NIT) {
            load_stage((it + 1) & 1, (it + 1) * KT);
            CP_COMMIT();
            CP_WAIT(1);
        } else {
            CP_WAIT(0);
        }
        __syncthreads();

        const float* as = &As[it & 1][0];
        const float* bs = &Bs[it & 1][0];
#pragma unroll
        for (int ks = 0; ks < KT; ks += 8) {
            uint32_t af[4][4];
#pragma unroll
            for (int mi = 0; mi < 4; mi++) {
                int rr = arow + mi * 16;
                af[mi][0] = tf32r_u(as[(rr     ) * SROW + ks + kq    ]);
                af[mi][1] = tf32r_u(as[(rr +  8) * SROW + ks + kq    ]);
                af[mi][2] = tf32r_u(as[(rr     ) * SROW + ks + kq + 4]);
                af[mi][3] = tf32r_u(as[(rr +  8) * SROW + ks + kq + 4]);
            }
            uint32_t bf[4][2];
#pragma unroll
            for (int ni = 0; ni < 4; ni++) {
                int cc = bcol + ni * 8;
                bf[ni][0] = __float_as_uint(bs[cc * SROW + ks + kq    ]);
                bf[ni][1] = __float_as_uint(bs[cc * SROW + ks + kq + 4]);
            }
#pragma unroll
            for (int mi = 0; mi < 4; mi++)
#pragma unroll
                for (int ni = 0; ni < 4; ni++)
                    mma_tf32(acc[mi][ni], af[mi], bf[ni]);
        }
        __syncthreads();
    }

    // ---- epilogue: bias + (optional) head-layout scatter ----
#pragma unroll
    for (int mi = 0; mi < 4; mi++) {
        const int r_lo = row0 + wm * 64 + mi * 16 + (lane >> 2);
        const int r_hi = r_lo + 8;
#pragma unroll
        for (int ni = 0; ni < 4; ni++) {
            const int n = col0 + wn * 32 + ni * 8 + (lane & 3) * 2;
            const float2 bv = *(const float2*)(bias + n);
            float2 lo = make_float2(acc[mi][ni][0] + bv.x, acc[mi][ni][1] + bv.y);
            float2 hi = make_float2(acc[mi][ni][2] + bv.x, acc[mi][ni][3] + bv.y);
            if (mode == 0) {
                *(float2*)(C + (size_t)r_lo * DM + n) = lo;
                *(float2*)(C + (size_t)r_hi * DM + n) = hi;
            } else {
                const int h = n >> 6, dk = n & (DK - 1);
                {
                    int bb = r_lo >> 11, t = r_lo & (T - 1);
                    *(float2*)(C + (((size_t)(bb*NH + h))*T + t)*DK + dk) = lo;
                }
                {
                    int bb = r_hi >> 11, t = r_hi & (T - 1);
                    *(float2*)(C + (((size_t)(bb*NH + h))*T + t)*DK + dk) = hi;
                }
            }
        }
    }
}

// ---------------- Flash attention: 1 thread = 1 query row --------------------
__global__ __launch_bounds__(128, 2)
void flash_attn(const float* __restrict__ Q, const float* __restrict__ K,
                const float* __restrict__ V, const int* __restrict__ mask,
                float* __restrict__ O) {
    const int qt = blockIdx.x, h = blockIdx.y, b = blockIdx.z;
    const int bh = b*NH + h;
    const int tid = threadIdx.x;
    const int q = qt*128 + tid;

    __shared__ float Ks[32][DK];
    __shared__ float Vs[32][DK];

    float qreg[DK];
    const float* qrow = Q + ((size_t)bh*T + q)*DK;
#pragma unroll
    for (int d = 0; d < DK; d += 4) {
        float4 v4 = *(const float4*)(qrow + d);
        qreg[d] = v4.x; qreg[d+1] = v4.y; qreg[d+2] = v4.z; qreg[d+3] = v4.w;
    }
    float acc[DK];
#pragma unroll
    for (int d = 0; d < DK; d++) acc[d] = 0.f;
    float mval = -1e30f, l = 0.f;

    const float* Kb = K + (size_t)bh*T*DK;
    const float* Vb = V + (size_t)bh*T*DK;
    const int*   mrow = mask + (size_t)q*T;

    for (int k0 = 0; k0 < T; k0 += 32) {
        __syncthreads();
        for (int i = tid; i < 512; i += 128) {
            int r = i >> 4;
            int c = (i & 15) << 2;
            *(float4*)&Ks[r][c] = *(const float4*)(Kb + (size_t)(k0+r)*DK + c);
            *(float4*)&Vs[r][c] = *(const float4*)(Vb + (size_t)(k0+r)*DK + c);
        }
        __syncthreads();

        float s[32];
#pragma unroll
        for (int j = 0; j < 32; j++) {
            float sv = 0.f;
#pragma unroll
            for (int d = 0; d < DK; d += 4) {
                float4 kv = *(const float4*)&Ks[j][d];
                sv += qreg[d]*kv.x + qreg[d+1]*kv.y
                    + qreg[d+2]*kv.z + qreg[d+3]*kv.w;
            }
            s[j] = (mrow[k0 + j] == 0) ? -1e9f : sv * 0.125f;
        }
        float tm = mval;
#pragma unroll
        for (int j = 0; j < 32; j++) tm = fmaxf(tm, s[j]);
        float corr = __expf(mval - tm);
        mval = tm;
        l *= corr;
#pragma unroll
        for (int d = 0; d < DK; d++) acc[d] *= corr;
#pragma unroll
        for (int j = 0; j < 32; j++) {
            float p = __expf(s[j] - tm);
            l += p;
#pragma unroll
            for (int d = 0; d < DK; d += 4) {
                float4 vv = *(const float4*)&Vs[j][d];
                acc[d]   += p*vv.x; acc[d+1] += p*vv.y;
                acc[d+2] += p*vv.z; acc[d+3] += p*vv.w;
            }
        }
    }

    const float inv = 1.f / l;
    float* orow = O + ((size_t)(b*T + q))*DM + h*DK;
#pragma unroll
    for (int d = 0; d < DK; d += 4) {
        float4 o4 = make_float4(tf32r(acc[d]*inv), tf32r(acc[d+1]*inv),
                                tf32r(acc[d+2]*inv), tf32r(acc[d+3]*inv));
        *(float4*)(orow + d) = o4;
    }
}

// ---------------- launch ----------------
extern "C" void kernel_launch(void* const* d_in, const int* in_sizes, int n_in,
                              void* d_out, int out_size) {
    const float* q    = (const float*)d_in[0];
    const float* k    = (const float*)d_in[1];
    const float* v    = (const float*)d_in[2];
    const int*   mask = (const int*)  d_in[3];
    const float* Wq = (const float*)d_in[4],  *bq = (const float*)d_in[5];
    const float* Aq = (const float*)d_in[6],  *Bq = (const float*)d_in[7];
    const float* Wk = (const float*)d_in[8],  *bk = (const float*)d_in[9];
    const float* Ak = (const float*)d_in[10], *Bk = (const float*)d_in[11];
    const float* Wv = (const float*)d_in[12], *bv = (const float*)d_in[13];
    const float* Av = (const float*)d_in[14], *Bv = (const float*)d_in[15];
    const float* Wo = (const float*)d_in[16], *bo = (const float*)d_in[17];
    float* out = (float*)d_out;

    float *weff, *wo, *qkv, *attn;
    cudaGetSymbolAddress((void**)&weff, g_weff);
    cudaGetSymbolAddress((void**)&wo,   g_wo);
    cudaGetSymbolAddress((void**)&qkv,  g_qkv);
    cudaGetSymbolAddress((void**)&attn, g_attn);

    float* weffq = weff;
    float* weffk = weff + (size_t)DM*DM;
    float* weffv = weff + (size_t)2*DM*DM;
    const size_t QKV_SZ = (size_t)BATCH*NH*T*DK;
    float* Qp = qkv;
    float* Kp = qkv + QKV_SZ;
    float* Vp = qkv + 2*QKV_SZ;

    weff_kernel<<<DM*DM/256, 256>>>(Wq, Aq, Bq, weffq);
    weff_kernel<<<DM*DM/256, 256>>>(Wk, Ak, Bk, weffk);
    weff_kernel<<<DM*DM/256, 256>>>(Wv, Av, Bv, weffv);
    round_tf32_kernel<<<DM*DM/4/256, 256>>>(Wo, wo, DM*DM/4);

    dim3 gg(DM/128, MTOT/128);     // 8 x 32
    gemm_mma<<<gg, 256>>>(q, weffq, bq, Qp, 1);
    gemm_mma<<<gg, 256>>>(k, weffk, bk, Kp, 1);
    gemm_mma<<<gg, 256>>>(v, weffv, bv, Vp, 1);

    flash_attn<<<dim3(T/128, NH, BATCH), 128>>>(Qp, Kp, Vp, mask, attn);

    gemm_mma<<<gg, 256>>>(attn, wo, bo, out, 0);
}

// round 4
// speedup vs baseline: 4.0279x; 2.9719x over previous
#include <cuda_runtime.h>
#include <math.h>
#include <stdint.h>

#define BATCH 2
#define T 2048
#define DM 1024
#define NH 16
#define DK 64
#define RR 8
#define LORA_SCALE 2.0f
#define MTOT (BATCH*T)      // 4096

// ---------------- scratch (device globals; no allocs allowed) ----------------
__device__ float g_weff[3][DM*DM];            // folded + tf32-rounded LoRA weights
__device__ float g_wo[DM*DM];                 // tf32-rounded Wo
__device__ float g_qkv[3][BATCH*NH*T*DK];     // Q,K,V in (b,h,t,d)
__device__ float g_attn[MTOT*DM];             // attention out
__device__ int   g_anyzero;                   // 1 if mask has any zero

// ---------------- helpers ----------------
__device__ __forceinline__ float tf32r(float x) {
    uint32_t r;
    asm("cvt.rna.tf32.f32 %0, %1;" : "=r"(r) : "f"(x));
    return __uint_as_float(r);
}
__device__ __forceinline__ uint32_t tf32r_u(float x) {
    uint32_t r;
    asm("cvt.rna.tf32.f32 %0, %1;" : "=r"(r) : "f"(x));
    return r;
}
#define CP_ASYNC16(dst, src) \
    asm volatile("cp.async.cg.shared.global [%0], [%1], 16;" :: "r"(dst), "l"(src))
#define CP_COMMIT() asm volatile("cp.async.commit_group;" ::: "memory")
#define CP_WAIT(n)  asm volatile("cp.async.wait_group %0;" :: "n"(n) : "memory")

__device__ __forceinline__ uint32_t smem_u32(const void* p) {
    uint32_t a;
    asm("{ .reg .u64 t; cvta.to.shared.u64 t, %1; cvt.u32.u64 %0, t; }" : "=r"(a) : "l"(p));
    return a;
}
__device__ __forceinline__ void mma_tf32(float* c, const uint32_t* a, const uint32_t* b) {
    asm volatile(
        "mma.sync.aligned.m16n8k8.row.col.f32.tf32.tf32.f32 "
        "{%0,%1,%2,%3}, {%4,%5,%6,%7}, {%8,%9}, {%0,%1,%2,%3};"
        : "+f"(c[0]), "+f"(c[1]), "+f"(c[2]), "+f"(c[3])
        : "r"(a[0]), "r"(a[1]), "r"(a[2]), "r"(a[3]), "r"(b[0]), "r"(b[1]));
}
__device__ __forceinline__ void mma_tf32b(float* c, const uint32_t* a,
                                          uint32_t b0, uint32_t b1) {
    asm volatile(
        "mma.sync.aligned.m16n8k8.row.col.f32.tf32.tf32.f32 "
        "{%0,%1,%2,%3}, {%4,%5,%6,%7}, {%8,%9}, {%0,%1,%2,%3};"
        : "+f"(c[0]), "+f"(c[1]), "+f"(c[2]), "+f"(c[3])
        : "r"(a[0]), "r"(a[1]), "r"(a[2]), "r"(a[3]), "r"(b0), "r"(b1));
}

// ---------------- mask scan ----------------
__global__ void maskscan_init() { g_anyzero = 0; }
__global__ void maskscan(const int* __restrict__ mask, int n) {
    int i = blockIdx.x * 256 + threadIdx.x;
    int z = 0;
    for (int k = i; k < n; k += gridDim.x * 256) z |= (mask[k] == 0);
    if (__any_sync(0xffffffffu, z) && (threadIdx.x & 31) == 0)
        atomicOr(&g_anyzero, 1);
}

// ---------------- W_eff = tf32_round(W + scale * B @ A) ----------------
__global__ void weff_kernel(const float* __restrict__ W,
                            const float* __restrict__ A,
                            const float* __restrict__ Bm,
                            float* __restrict__ out) {
    int idx = blockIdx.x * 256 + threadIdx.x;
    int o = idx >> 10;
    int d = idx & 1023;
    float s = 0.f;
#pragma unroll
    for (int r = 0; r < RR; r++) s += Bm[o*RR + r] * A[r*DM + d];
    out[idx] = tf32r(W[idx] + LORA_SCALE * s);
}

__global__ void round_tf32_kernel(const float* __restrict__ in,
                                  float* __restrict__ out, int n4) {
    int i = blockIdx.x * 256 + threadIdx.x;
    if (i >= n4) return;
    float4 v = ((const float4*)in)[i];
    v.x = tf32r(v.x); v.y = tf32r(v.y); v.z = tf32r(v.z); v.w = tf32r(v.w);
    ((float4*)out)[i] = v;
}

// ---------------- mma.sync tf32 GEMM (unchanged from R3) --------------------
#define KT 16
#define NIT (DM / KT)         // 64
#define SROW 20

__global__ __launch_bounds__(256, 2)
void gemm_mma(const float* __restrict__ A, const float* __restrict__ W,
              const float* __restrict__ bias, float* __restrict__ C, int mode) {
    __shared__ float As[2][128 * SROW];
    __shared__ float Bs[2][128 * SROW];

    const int tid = threadIdx.x;
    const int wid = tid >> 5;
    const int lane = tid & 31;
    const int wm = wid >> 2;
    const int wn = wid & 3;
    const int row0 = blockIdx.y * 128;
    const int col0 = blockIdx.x * 128;

    const uint32_t sa = smem_u32(&As[0][0]);
    const uint32_t sb = smem_u32(&Bs[0][0]);
    const int e0 = tid * 2;
    float acc[4][4][4];
#pragma unroll
    for (int i = 0; i < 4; i++)
#pragma unroll
        for (int j = 0; j < 4; j++)
#pragma unroll
            for (int r = 0; r < 4; r++) acc[i][j][r] = 0.f;

    auto load_stage = [&](int st, int k0) {
#pragma unroll
        for (int i = 0; i < 2; i++) {
            int e = e0 + i;
            int r = e >> 2;
            int c4 = (e & 3) * 4;
            uint32_t doff = (uint32_t)(r * SROW + c4) * 4;
            CP_ASYNC16(sa + (uint32_t)st * (128*SROW*4) + doff,
                       A + (size_t)(row0 + r) * DM + k0 + c4);
            CP_ASYNC16(sb + (uint32_t)st * (128*SROW*4) + doff,
                       W + (size_t)(col0 + r) * DM + k0 + c4);
        }
    };

    load_stage(0, 0);
    CP_COMMIT();

    const int arow = wm * 64 + (lane >> 2);
    const int bcol = wn * 32 + (lane >> 2);
    const int kq = lane & 3;

    for (int it = 0; it < NIT; it++) {
        if (it + 1 < NIT) {
            load_stage((it + 1) & 1, (it + 1) * KT);
            CP_COMMIT();
            CP_WAIT(1);
        } else {
            CP_WAIT(0);
        }
        __syncthreads();

        const float* as = &As[it & 1][0];
        const float* bs = &Bs[it & 1][0];
#pragma unroll
        for (int ks = 0; ks < KT; ks += 8) {
            uint32_t af[4][4];
#pragma unroll
            for (int mi = 0; mi < 4; mi++) {
                int rr = arow + mi * 16;
                af[mi][0] = tf32r_u(as[(rr     ) * SROW + ks + kq    ]);
                af[mi][1] = tf32r_u(as[(rr +  8) * SROW + ks + kq    ]);
                af[mi][2] = tf32r_u(as[(rr     ) * SROW + ks + kq + 4]);
                af[mi][3] = tf32r_u(as[(rr +  8) * SROW + ks + kq + 4]);
            }
            uint32_t bf[4][2];
#pragma unroll
            for (int ni = 0; ni < 4; ni++) {
                int cc = bcol + ni * 8;
                bf[ni][0] = __float_as_uint(bs[cc * SROW + ks + kq    ]);
                bf[ni][1] = __float_as_uint(bs[cc * SROW + ks + kq + 4]);
            }
#pragma unroll
            for (int mi = 0; mi < 4; mi++)
#pragma unroll
                for (int ni = 0; ni < 4; ni++)
                    mma_tf32(acc[mi][ni], af[mi], bf[ni]);
        }
        __syncthreads();
    }

#pragma unroll
    for (int mi = 0; mi < 4; mi++) {
        const int r_lo = row0 + wm * 64 + mi * 16 + (lane >> 2);
        const int r_hi = r_lo + 8;
#pragma unroll
        for (int ni = 0; ni < 4; ni++) {
            const int n = col0 + wn * 32 + ni * 8 + (lane & 3) * 2;
            const float2 bv = *(const float2*)(bias + n);
            float2 lo = make_float2(acc[mi][ni][0] + bv.x, acc[mi][ni][1] + bv.y);
            float2 hi = make_float2(acc[mi][ni][2] + bv.x, acc[mi][ni][3] + bv.y);
            if (mode == 0) {
                *(float2*)(C + (size_t)r_lo * DM + n) = lo;
                *(float2*)(C + (size_t)r_hi * DM + n) = hi;
            } else {
                const int h = n >> 6, dk = n & (DK - 1);
                {
                    int bb = r_lo >> 11, t = r_lo & (T - 1);
                    *(float2*)(C + (((size_t)(bb*NH + h))*T + t)*DK + dk) = lo;
                }
                {
                    int bb = r_hi >> 11, t = r_hi & (T - 1);
                    *(float2*)(C + (((size_t)(bb*NH + h))*T + t)*DK + dk) = hi;
                }
            }
        }
    }
}

// ---------------- tensor-core flash attention --------------------------------
// CTA: 256 thr (8 warps), one (b,h), 128 q rows; warp = 16 q rows.
// K/V tiles of 64 keys, double-buffered cp.async.
// smem pool: per buffer K 64x68 (17408B) + V 64x72 (18432B) = 35840B, x2.
// Q staged once at pool[0] with stride 68 (34816B), consumed before K/V use.
#define KSTRIDE 68
#define VSTRIDE 72
#define KBYTES 17408
#define BUFBYTES 35840
#define FA_SMEM (2*BUFBYTES)    // 71680
#define NT_TILES (T/64)         // 32

__global__ __launch_bounds__(256, 2)
void flash_mma(const float* __restrict__ Q, const float* __restrict__ K,
               const float* __restrict__ V, const int* __restrict__ mask,
               float* __restrict__ O) {
    extern __shared__ float pool[];
    const int tid = threadIdx.x, wid = tid >> 5, lane = tid & 31;
    const int qt = blockIdx.x, h = blockIdx.y, b = blockIdx.z;
    const int bh = b*NH + h;
    const int r = lane >> 2, qd = lane & 3;
    const int anyz = g_anyzero;
    const uint32_t pbase = smem_u32(pool);

    // ---- stage Q, build register fragments (scale 1/8 folded) ----
    {
        const float* Qg = Q + ((size_t)bh*T + (size_t)qt*128)*DK;
#pragma unroll
        for (int i = 0; i < 8; i++) {
            int e = tid + i*256;
            int row = e >> 4, c4 = (e & 15) * 4;
            CP_ASYNC16(pbase + row*(KSTRIDE*4) + c4*4, Qg + row*64 + c4);
        }
        CP_COMMIT(); CP_WAIT(0);
    }
    __syncthreads();
    uint32_t qf[8][4];
    {
        const int r0 = wid*16 + r;
#pragma unroll
        for (int ks = 0; ks < 8; ks++) {
            qf[ks][0] = tf32r_u(pool[(r0    )*KSTRIDE + ks*8 + qd    ] * 0.125f);
            qf[ks][1] = tf32r_u(pool[(r0 + 8)*KSTRIDE + ks*8 + qd    ] * 0.125f);
            qf[ks][2] = tf32r_u(pool[(r0    )*KSTRIDE + ks*8 + qd + 4] * 0.125f);
            qf[ks][3] = tf32r_u(pool[(r0 + 8)*KSTRIDE + ks*8 + qd + 4] * 0.125f);
        }
    }
    __syncthreads();

    const float* Kg = K + (size_t)bh*T*DK;
    const float* Vg = V + (size_t)bh*T*DK;

    auto loadKV = [&](int kt, int bufb) {
        const float* kg = Kg + (size_t)kt*64*DK;
        const float* vg = Vg + (size_t)kt*64*DK;
        uint32_t kb = pbase + (uint32_t)bufb * BUFBYTES;
        uint32_t vb = kb + KBYTES;
#pragma unroll
        for (int i = 0; i < 4; i++) {
            int e = tid + i*256;
            int row = e >> 4, c4 = (e & 15) * 4;
            CP_ASYNC16(kb + row*(KSTRIDE*4) + c4*4, kg + row*64 + c4);
            CP_ASYNC16(vb + row*(VSTRIDE*4) + c4*4, vg + row*64 + c4);
        }
    };

    float m_lo = -1e30f, m_hi = -1e30f, l_lo = 0.f, l_hi = 0.f;
    float oacc[8][4];
#pragma unroll
    for (int i = 0; i < 8; i++)
#pragma unroll
        for (int j = 0; j < 4; j++) oacc[i][j] = 0.f;

    const int q0 = qt*128 + wid*16;
    const int s1 = (lane & 28) | (qd >> 1);
    const int s2 = s1 + 2;
    const bool odd = (qd & 1) != 0;

    loadKV(0, 0);
    CP_COMMIT();

    for (int kt = 0; kt < NT_TILES; kt++) {
        const int buf = kt & 1;
        if (kt + 1 < NT_TILES) {
            loadKV(kt + 1, buf ^ 1);
            CP_COMMIT();
            CP_WAIT(1);
        } else {
            CP_WAIT(0);
        }
        __syncthreads();

        const float* ksm = pool + buf * (BUFBYTES/4);
        const float* vsm = ksm + (KBYTES/4);

        // ---- S = Q K^T ----
        float sa[8][4];
#pragma unroll
        for (int i = 0; i < 8; i++)
#pragma unroll
            for (int j = 0; j < 4; j++) sa[i][j] = 0.f;
#pragma unroll
        for (int ks = 0; ks < 8; ks++) {
#pragma unroll
            for (int nt = 0; nt < 8; nt++) {
                uint32_t b0 = tf32r_u(ksm[(nt*8 + r)*KSTRIDE + ks*8 + qd    ]);
                uint32_t b1 = tf32r_u(ksm[(nt*8 + r)*KSTRIDE + ks*8 + qd + 4]);
                mma_tf32b(sa[nt], qf[ks], b0, b1);
            }
        }

        // ---- mask (skipped when mask is all ones) ----
        if (anyz) {
#pragma unroll
            for (int nt = 0; nt < 8; nt++) {
                const int col = kt*64 + nt*8 + qd*2;
                int2 mlo = *(const int2*)(mask + (size_t)(q0 + r    )*T + col);
                int2 mhi = *(const int2*)(mask + (size_t)(q0 + r + 8)*T + col);
                if (mlo.x == 0) sa[nt][0] = -1e9f;
                if (mlo.y == 0) sa[nt][1] = -1e9f;
                if (mhi.x == 0) sa[nt][2] = -1e9f;
                if (mhi.y == 0) sa[nt][3] = -1e9f;
            }
        }

        // ---- online softmax (rows live in quads) ----
        float tm_lo = m_lo, tm_hi = m_hi;
#pragma unroll
        for (int nt = 0; nt < 8; nt++) {
            tm_lo = fmaxf(tm_lo, fmaxf(sa[nt][0], sa[nt][1]));
            tm_hi = fmaxf(tm_hi, fmaxf(sa[nt][2], sa[nt][3]));
        }
        tm_lo = fmaxf(tm_lo, __shfl_xor_sync(0xffffffffu, tm_lo, 1));
        tm_lo = fmaxf(tm_lo, __shfl_xor_sync(0xffffffffu, tm_lo, 2));
        tm_hi = fmaxf(tm_hi, __shfl_xor_sync(0xffffffffu, tm_hi, 1));
        tm_hi = fmaxf(tm_hi, __shfl_xor_sync(0xffffffffu, tm_hi, 2));
        const float corr_lo = __expf(m_lo - tm_lo);
        const float corr_hi = __expf(m_hi - tm_hi);
        m_lo = tm_lo; m_hi = tm_hi;

        float suml_lo = 0.f, suml_hi = 0.f;
#pragma unroll
        for (int nt = 0; nt < 8; nt++) {
            sa[nt][0] = __expf(sa[nt][0] - m_lo);
            sa[nt][1] = __expf(sa[nt][1] - m_lo);
            sa[nt][2] = __expf(sa[nt][2] - m_hi);
            sa[nt][3] = __expf(sa[nt][3] - m_hi);
            suml_lo += sa[nt][0] + sa[nt][1];
            suml_hi += sa[nt][2] + sa[nt][3];
        }
        suml_lo += __shfl_xor_sync(0xffffffffu, suml_lo, 1);
        suml_lo += __shfl_xor_sync(0xffffffffu, suml_lo, 2);
        suml_hi += __shfl_xor_sync(0xffffffffu, suml_hi, 1);
        suml_hi += __shfl_xor_sync(0xffffffffu, suml_hi, 2);
        l_lo = l_lo * corr_lo + suml_lo;
        l_hi = l_hi * corr_hi + suml_hi;
#pragma unroll
        for (int nt = 0; nt < 8; nt++) {
            oacc[nt][0] *= corr_lo; oacc[nt][1] *= corr_lo;
            oacc[nt][2] *= corr_hi; oacc[nt][3] *= corr_hi;
        }

        // ---- O += P V  (P C-frag -> A-frag via warp shuffles) ----
#pragma unroll
        for (int j = 0; j < 8; j++) {
            float x0 = __shfl_sync(0xffffffffu, sa[j][0], s1);
            float x1 = __shfl_sync(0xffffffffu, sa[j][1], s1);
            float x2 = __shfl_sync(0xffffffffu, sa[j][2], s1);
            float x3 = __shfl_sync(0xffffffffu, sa[j][3], s1);
            float y0 = __shfl_sync(0xffffffffu, sa[j][0], s2);
            float y1 = __shfl_sync(0xffffffffu, sa[j][1], s2);
            float y2 = __shfl_sync(0xffffffffu, sa[j][2], s2);
            float y3 = __shfl_sync(0xffffffffu, sa[j][3], s2);
            uint32_t af[4];
            af[0] = tf32r_u(odd ? x1 : x0);
            af[1] = tf32r_u(odd ? x3 : x2);
            af[2] = tf32r_u(odd ? y1 : y0);
            af[3] = tf32r_u(odd ? y3 : y2);
#pragma unroll
            for (int nt = 0; nt < 8; nt++) {
                uint32_t b0 = tf32r_u(vsm[(j*8 + qd    )*VSTRIDE + nt*8 + r]);
                uint32_t b1 = tf32r_u(vsm[(j*8 + qd + 4)*VSTRIDE + nt*8 + r]);
                mma_tf32b(oacc[nt], af, b0, b1);
            }
        }
        __syncthreads();
    }

    // ---- epilogue: O -> (b, t, h*64+d) ----
    const float ilo = 1.f / l_lo;
    const float ihi = 1.f / l_hi;
#pragma unroll
    for (int nt = 0; nt < 8; nt++) {
        const int col = h*64 + nt*8 + qd*2;
        float2 lo = make_float2(oacc[nt][0]*ilo, oacc[nt][1]*ilo);
        float2 hi = make_float2(oacc[nt][2]*ihi, oacc[nt][3]*ihi);
        *(float2*)(O + (size_t)(b*T + q0 + r    )*DM + col) = lo;
        *(float2*)(O + (size_t)(b*T + q0 + r + 8)*DM + col) = hi;
    }
}

// ---------------- launch ----------------
extern "C" void kernel_launch(void* const* d_in, const int* in_sizes, int n_in,
                              void* d_out, int out_size) {
    const float* q    = (const float*)d_in[0];
    const float* k    = (const float*)d_in[1];
    const float* v    = (const float*)d_in[2];
    const int*   mask = (const int*)  d_in[3];
    const float* Wq = (const float*)d_in[4],  *bq = (const float*)d_in[5];
    const float* Aq = (const float*)d_in[6],  *Bq = (const float*)d_in[7];
    const float* Wk = (const float*)d_in[8],  *bk = (const float*)d_in[9];
    const float* Ak = (const float*)d_in[10], *Bk = (const float*)d_in[11];
    const float* Wv = (const float*)d_in[12], *bv = (const float*)d_in[13];
    const float* Av = (const float*)d_in[14], *Bv = (const float*)d_in[15];
    const float* Wo = (const float*)d_in[16], *bo = (const float*)d_in[17];
    float* out = (float*)d_out;

    float *weff, *wo, *qkv, *attn;
    cudaGetSymbolAddress((void**)&weff, g_weff);
    cudaGetSymbolAddress((void**)&wo,   g_wo);
    cudaGetSymbolAddress((void**)&qkv,  g_qkv);
    cudaGetSymbolAddress((void**)&attn, g_attn);

    float* weffq = weff;
    float* weffk = weff + (size_t)DM*DM;
    float* weffv = weff + (size_t)2*DM*DM;
    const size_t QKV_SZ = (size_t)BATCH*NH*T*DK;
    float* Qp = qkv;
    float* Kp = qkv + QKV_SZ;
    float* Vp = qkv + 2*QKV_SZ;

    cudaFuncSetAttribute(flash_mma, cudaFuncAttributeMaxDynamicSharedMemorySize, FA_SMEM);

    maskscan_init<<<1, 1>>>();
    maskscan<<<4096, 256>>>(mask, T*T);

    weff_kernel<<<DM*DM/256, 256>>>(Wq, Aq, Bq, weffq);
    weff_kernel<<<DM*DM/256, 256>>>(Wk, Ak, Bk, weffk);
    weff_kernel<<<DM*DM/256, 256>>>(Wv, Av, Bv, weffv);
    round_tf32_kernel<<<DM*DM/4/256, 256>>>(Wo, wo, DM*DM/4);

    dim3 gg(DM/128, MTOT/128);     // 8 x 32
    gemm_mma<<<gg, 256>>>(q, weffq, bq, Qp, 1);
    gemm_mma<<<gg, 256>>>(k, weffk, bk, Kp, 1);
    gemm_mma<<<gg, 256>>>(v, weffv, bv, Vp, 1);

    flash_mma<<<dim3(T/128, NH, BATCH), 256, FA_SMEM>>>(Qp, Kp, Vp, mask, attn);

    gemm_mma<<<gg, 256>>>(attn, wo, bo, out, 0);
}